// round 6
// baseline (speedup 1.0000x reference)
#include <cuda_runtime.h>
#include <stdint.h>

// ---------------- problem constants ----------------
#define NC    80
#define A0    4096
#define A1    1024
#define A2    256
#define N0    (A0*NC)          // 327680
#define N1    (A1*NC)          // 81920
#define N2    (A2*NC)          // 20480
#define TOT   (N0+N1+N2)       // 430080 per image
#define OFF1  N0
#define OFF2  (N0+N1)
#define NB    8
#define TOPK  1000
#define NLVL  3
#define NPAIR (NB*NLVL)        // 24
#define CAND  3000
#define DETS  100
#define IMGSZ 2048.0f
#define NMS_T 0.6f
#define CAP   4096
#define BINS  16512            // key16 range: ~f2k(w>=1) >> 16 in [127, 16511]
#define NMSCAP 256             // fast-path capacity per class (avg ~37)

// dynamic smem for k_sortlevel: union of hist (BINS u32) and sort buffer (CAP u64)
#define DYNBYTES ((BINS*4 > CAP*8) ? BINS*4 : CAP*8)

// ---------------- scratch (device globals; no allocations) ----------------
__device__ __align__(16) unsigned short g_keys16[NB*TOT]; // ~6.9 MB
__device__ float    g_score[NB*CAND];
__device__ int      g_labelv[NB*CAND];
__device__ float    g_boxv[NB*CAND*4];
__device__ int      g_rank2pos[NB*CAND];
__device__ float    g_ss[NB*CAND];
__device__ int      g_lab_ranked[NB*CAND];
__device__ unsigned char g_keep[NB*CAND];

// ---------------- helpers ----------------
__device__ __forceinline__ uint32_t f2k(float f){
    uint32_t u = __float_as_uint(f);
    return (u & 0x80000000u) ? ~u : (u | 0x80000000u);
}
__device__ __forceinline__ float k2f(uint32_t k){
    uint32_t u = (k & 0x80000000u) ? (k ^ 0x80000000u) : ~k;
    return __uint_as_float(u);
}
// exact path: XLA logistic(x) == 0.5 + 0.5*tanh(0.5*x)
__device__ __forceinline__ float sigm(float x){
    return 0.5f*tanhf(0.5f*x) + 0.5f;
}

// bitonic sort (ascending) of n (2048 or 4096) u64s, blockDim = 1024
__device__ __forceinline__ void bitonicN(unsigned long long* s, int n){
    const int tid = threadIdx.x;
    const int per = n >> 10;
    for (int k = 2; k <= n; k <<= 1){
        for (int j = k >> 1; j > 0; j >>= 1){
            __syncthreads();
            for (int w = 0; w < per; ++w){
                int i   = tid + (w << 10);
                int ixj = i ^ j;
                if (ixj > i){
                    unsigned long long a = s[i], bb = s[ixj];
                    bool up = ((i & k) == 0);
                    if ((a > bb) == up){ s[i] = bb; s[ixj] = a; }
                }
            }
        }
    }
    __syncthreads();
}

// ---------------- kernels ----------------
// pure streaming pass: surrogate 16-bit keys, NO atomics
// surrogate: w = (1+e^-c)(1+e^-t); score order == descending w (monotone)
__global__ __launch_bounds__(256) void k_scores(
    const float* __restrict__ cls0, const float* __restrict__ cls1, const float* __restrict__ cls2,
    const float* __restrict__ ctr0, const float* __restrict__ ctr1, const float* __restrict__ ctr2)
{
    const int b = blockIdx.y;
    const int base = blockIdx.x*2048 + threadIdx.x*8;   // blocks never straddle levels; 8-runs never straddle anchors
    int j0, A; const float* cls; const float* ctr;
    if (base < OFF1){ j0 = base;        cls = cls0; ctr = ctr0; A = A0; }
    else if (base < OFF2){ j0 = base - OFF1; cls = cls1; ctr = ctr1; A = A1; }
    else { j0 = base - OFF2; cls = cls2; ctr = ctr2; A = A2; }

    float tv = __ldg(ctr + (size_t)b*A + j0/NC);
    float et = __expf(-tv);
    float vt = et + 1.0f;

    const float4* cp = (const float4*)(cls + (size_t)b*A*NC + j0);
    float4 ca = cp[0], cb = cp[1];
    float cv[8] = {ca.x, ca.y, ca.z, ca.w, cb.x, cb.y, cb.z, cb.w};

    uint32_t ks[8];
    #pragma unroll
    for (int e = 0; e < 8; ++e){
        float ec = __expf(-cv[e]);
        float w  = fmaf(ec, vt, vt);                        // (1+ec)*vt
        ks[e] = ((~__float_as_uint(w)) & 0x7FFFFFFFu) >> 16; // = ~f2k(w)>>16, w>0
    }
    uint4 pk;
    pk.x = ks[0] | (ks[1] << 16);
    pk.y = ks[2] | (ks[3] << 16);
    pk.z = ks[4] | (ks[5] << 16);
    pk.w = ks[6] | (ks[7] << 16);
    *(uint4*)(g_keys16 + (size_t)b*TOT + base) = pk;
}

// per (image,level): shared hist + pivot + collect + exact rescore + sort + decode top-1000
__global__ __launch_bounds__(1024) void k_sortlevel(
    const float* __restrict__ cls0, const float* __restrict__ cls1, const float* __restrict__ cls2,
    const float* __restrict__ ctr0, const float* __restrict__ ctr1, const float* __restrict__ ctr2,
    const float* __restrict__ reg0, const float* __restrict__ reg1, const float* __restrict__ reg2,
    const float* __restrict__ anc0, const float* __restrict__ anc1, const float* __restrict__ anc2)
{
    extern __shared__ unsigned char dynsmem[];
    uint32_t*           hist = (uint32_t*)dynsmem;           // phase A (BINS u32)
    unsigned long long* s64  = (unsigned long long*)dynsmem; // phase B+ (CAP u64), aliases hist
    __shared__ uint32_t ssum[1024];
    __shared__ int sP, sCum, sThresh, sCnt;

    const int p = blockIdx.x, b = p/NLVL, l = p%NLVL;
    const int tid = threadIdx.x;
    int A, offl; const float *cls, *ctr, *reg, *anc;
    if (l == 0){ A=A0; offl=0;    cls=cls0; ctr=ctr0; reg=reg0; anc=anc0; }
    else if (l == 1){ A=A1; offl=OFF1; cls=cls1; ctr=ctr1; reg=reg1; anc=anc1; }
    else { A=A2; offl=OFF2; cls=cls2; ctr=ctr2; reg=reg2; anc=anc2; }

    // ---- phase H: build local histogram from this pair's key slice (L2-resident)
    for (int t = tid; t < BINS; t += 1024) hist[t] = 0;
    __syncthreads();
    const uint4* kp = (const uint4*)(g_keys16 + (size_t)b*TOT + offl);
    const int num8 = (A*NC)/8;
    for (int v = tid; v < num8; v += 1024){
        uint4 q = kp[v];
        uint32_t wv[4] = {q.x, q.y, q.z, q.w};
        #pragma unroll
        for (int u = 0; u < 4; ++u){
            atomicAdd(hist + (wv[u] & 0xFFFFu), 1u);
            atomicAdd(hist + (wv[u] >> 16),     1u);
        }
    }
    __syncthreads();

    // ---- phase A: pivot bin (highest T with cum(bins>=T) >= TOPK), extend 1 bin if safe
    int lo = tid*17; if (lo > BINS) lo = BINS;
    int hi = lo + 17; if (hi > BINS) hi = BINS;
    uint32_t own = 0;
    for (int i = lo; i < hi; ++i) own += hist[i];
    ssum[tid] = own; __syncthreads();
    for (int off = 1; off < 1024; off <<= 1){
        uint32_t v = (tid + off < 1024) ? ssum[tid + off] : 0;
        __syncthreads(); ssum[tid] += v; __syncthreads();
    }
    uint32_t cumAbove = (tid < 1023) ? ssum[tid + 1] : 0;
    if (tid == 0) sCnt = 0;
    if (cumAbove < TOPK && cumAbove + own >= TOPK){
        uint32_t run = cumAbove; int P = lo;
        for (int i = hi - 1; i >= lo; --i){ run += hist[i]; if (run >= TOPK){ P = i; break; } }
        sP = P; sCum = (int)run;
    }
    __syncthreads();
    if (tid == 0){
        int P = sP, ext = P;
        if (P > 0 && sCum + (int)hist[P-1] <= CAP) ext = P - 1;
        sThresh = ext;
    }
    __syncthreads();
    const uint32_t thr = (uint32_t)sThresh;
    __syncthreads();   // all hist reads done before s64 overwrites it

    // ---- phase B: collect candidate indices (order arbitrary; fixed by sort)
    for (int v = tid; v < num8; v += 1024){
        uint4 q = kp[v];
        uint32_t wv[4] = {q.x, q.y, q.z, q.w};
        #pragma unroll
        for (int u = 0; u < 4; ++u){
            uint32_t l16 = wv[u] & 0xFFFFu, h16 = wv[u] >> 16;
            if (l16 >= thr){ int pos = atomicAdd(&sCnt, 1); if (pos < CAP) s64[pos] = (unsigned long long)(v*8 + u*2); }
            if (h16 >= thr){ int pos = atomicAdd(&sCnt, 1); if (pos < CAP) s64[pos] = (unsigned long long)(v*8 + u*2 + 1); }
        }
    }
    __syncthreads();
    int cnt = sCnt; if (cnt > CAP) cnt = CAP;
    const int SORTN = (cnt <= 2048) ? 2048 : 4096;

    // ---- phase C: exact XLA-matching scores; build (~key, idx) composites
    for (int i = tid; i < SORTN; i += 1024){
        unsigned long long comp = 0xFFFFFFFFFFFFFFFFULL;
        if (i < cnt){
            int j = (int)(uint32_t)s64[i];
            float c  = cls[(size_t)b*A*NC + j];
            float tt = ctr[(size_t)b*A + j/NC];
            float sa = sigm(c);
            float st = sigm(tt);
            float sc = sqrtf(__fmul_rn(sa, st));
            uint32_t key = (sc > 0.2f) ? f2k(sc) : 0x407FFFFFu;   // f2k(-1.0f)
            comp = ((unsigned long long)(~key) << 32) | (uint32_t)j;
        }
        s64[i] = comp;
    }
    bitonicN(s64, SORTN);

    // ---- phase E: emit sorted top-1000 + decode boxes
    if (tid < TOPK){
        unsigned long long cc = s64[tid];
        uint32_t key = ~(uint32_t)(cc >> 32);
        uint32_t idx = (uint32_t)cc;
        float sc = k2f(key);
        int aidx = (int)(idx / NC);
        int lab  = (int)(idx % NC);

        const int pos = b*CAND + l*TOPK + tid;
        g_score[pos]  = sc;
        g_labelv[pos] = lab;

        const float* a = anc + (size_t)aidx*4;
        const float* r = reg + ((size_t)b*A + aidx)*4;
        float a0 = a[0], a1 = a[1], a2 = a[2], a3 = a[3];
        float cx = __fmul_rn(0.5f, __fadd_rn(a0, a2));
        float cy = __fmul_rn(0.5f, __fadd_rn(a1, a3));
        float w  = __fsub_rn(a2, a0);
        float hh = __fsub_rn(a3, a1);
        float x1 = __fsub_rn(cx, __fmul_rn(r[0], w));
        float y1 = __fsub_rn(cy, __fmul_rn(r[1], hh));
        float x2 = __fadd_rn(cx, __fmul_rn(r[2], w));
        float y2 = __fadd_rn(cy, __fmul_rn(r[3], hh));
        x1 = fminf(fmaxf(x1, 0.0f), IMGSZ);
        y1 = fminf(fmaxf(y1, 0.0f), IMGSZ);
        x2 = fminf(fmaxf(x2, 0.0f), IMGSZ);
        y2 = fminf(fmaxf(y2, 0.0f), IMGSZ);
        g_boxv[pos*4+0] = x1; g_boxv[pos*4+1] = y1;
        g_boxv[pos*4+2] = x2; g_boxv[pos*4+3] = y2;
    }
}

// per (image,level): rank this level's 1000 against the other two (exact top_k ties)
__global__ __launch_bounds__(1024) void k_merge(){
    __shared__ float sc[CAND];
    const int p = blockIdx.x, b = p/NLVL, l = p%NLVL;
    const int tid = threadIdx.x;
    for (int t = tid; t < CAND; t += 1024) sc[t] = g_score[b*CAND + t];
    __syncthreads();
    if (tid < TOPK){
        const int t = l*TOPK + tid;
        float x = sc[t];
        int rank = tid;
        #pragma unroll
        for (int l2 = 0; l2 < NLVL; ++l2){
            if (l2 == l) continue;
            const float* arr = sc + l2*TOPK;
            int lo = 0, hi = TOPK;
            if (l2 < l){      // elements >= x precede (earlier global idx wins ties)
                while (lo < hi){ int m = (lo + hi) >> 1; if (arr[m] >= x) lo = m + 1; else hi = m; }
            } else {          // only elements > x precede
                while (lo < hi){ int m = (lo + hi) >> 1; if (arr[m] >  x) lo = m + 1; else hi = m; }
            }
            rank += lo;
        }
        g_rank2pos[b*CAND + rank]   = t;
        g_ss[b*CAND + rank]         = x;
        g_lab_ranked[b*CAND + rank] = g_labelv[b*CAND + t];
    }
}

// per (image,class) warp-level bitmask NMS: parallel IoU mask build + scalar bitmask scan
__global__ __launch_bounds__(32) void k_nms(){
    const int blk = blockIdx.x, b = blk/NC, c = blk%NC;
    const int lane = threadIdx.x;
    __shared__ short slab[CAND];                 // staged labels
    __shared__ short slist[CAND];                // class member ranks (rank-ordered)
    __shared__ float sx1[NMSCAP], sy1[NMSCAP], sx2[NMSCAP], sy2[NMSCAP];
    __shared__ uint32_t smask[NMSCAP*8];         // row i suppress-bitmask words
    __shared__ unsigned char skfb[CAND];         // fallback keep flags

    // stage labels to shared (independent coalesced loads)
    for (int r = lane; r < CAND; r += 32)
        slab[r] = (short)g_lab_ranked[b*CAND + r];
    __syncwarp();

    // ballot-compact class members in rank order
    int basec = 0;
    for (int r0 = 0; r0 < CAND; r0 += 32){
        int r = r0 + lane;
        bool m = (r < CAND) && (slab[r] == (short)c);
        unsigned bal = __ballot_sync(0xFFFFFFFFu, m);
        if (m) slist[basec + __popc(bal & ((1u << lane) - 1u))] = (short)r;
        basec += __popc(bal);
    }
    const int cnt = basec;
    if (cnt == 0) return;
    const float off = (float)c * 2049.0f;
    __syncwarp();

    if (cnt <= NMSCAP){
        // load offset boxes (offset rounding matches reference!)
        for (int m = lane; m < cnt; m += 32){
            int pos = g_rank2pos[b*CAND + slist[m]];
            sx1[m] = __fadd_rn(g_boxv[(b*CAND+pos)*4+0], off);
            sy1[m] = __fadd_rn(g_boxv[(b*CAND+pos)*4+1], off);
            sx2[m] = __fadd_rn(g_boxv[(b*CAND+pos)*4+2], off);
            sy2[m] = __fadd_rn(g_boxv[(b*CAND+pos)*4+3], off);
        }
        __syncwarp();
        const int nw = (cnt + 31) >> 5;

        // build suppress masks: row i = {j > i : iou(i,j) > thr}
        for (int i = 0; i < cnt; ++i){
            float ix1 = sx1[i], iy1 = sy1[i], ix2 = sx2[i], iy2 = sy2[i];
            float ia = __fmul_rn(__fsub_rn(ix2, ix1), __fsub_rn(iy2, iy1));
            for (int w = (i >> 5); w < nw; ++w){
                int j = (w << 5) + lane;
                bool sup = false;
                if (j > i && j < cnt){
                    float mx1 = sx1[j], my1 = sy1[j], mx2 = sx2[j], my2 = sy2[j];
                    float xx1 = fmaxf(ix1, mx1), yy1 = fmaxf(iy1, my1);
                    float xx2 = fminf(ix2, mx2), yy2 = fminf(iy2, my2);
                    float ww = fmaxf(__fsub_rn(xx2, xx1), 0.0f);
                    float hh = fmaxf(__fsub_rn(yy2, yy1), 0.0f);
                    float inter = __fmul_rn(ww, hh);
                    float ma  = __fmul_rn(__fsub_rn(mx2, mx1), __fsub_rn(my2, my1));
                    float uni = __fsub_rn(__fadd_rn(ia, ma), inter);
                    sup = (inter / uni > NMS_T);
                }
                unsigned bal = __ballot_sync(0xFFFFFFFFu, sup);
                if (lane == 0) smask[i*8 + w] = bal;
            }
        }
        __syncwarp();

        // scalar greedy bitmask scan (replicated across lanes; shared broadcasts)
        uint32_t sup[8] = {0,0,0,0,0,0,0,0};
        for (int i = 0; i < cnt; ++i){
            if (!((sup[i >> 5] >> (i & 31)) & 1u)){
                for (int w = (i >> 5); w < nw; ++w) sup[w] |= smask[i*8 + w];
            }
        }
        for (int w = 0; w < nw; ++w){
            int j = (w << 5) + lane;
            if (j < cnt)
                g_keep[b*CAND + slist[j]] = (unsigned char)(((~sup[w]) >> lane) & 1u);
        }
    } else {
        // generic fallback (not expected to trigger): serial greedy, boxes from global
        for (int m = lane; m < cnt; m += 32) skfb[m] = 1;
        __syncwarp();
        for (int i = 0; i < cnt; ++i){
            if (skfb[i]){
                int posi = g_rank2pos[b*CAND + slist[i]];
                float ix1 = __fadd_rn(g_boxv[(b*CAND+posi)*4+0], off);
                float iy1 = __fadd_rn(g_boxv[(b*CAND+posi)*4+1], off);
                float ix2 = __fadd_rn(g_boxv[(b*CAND+posi)*4+2], off);
                float iy2 = __fadd_rn(g_boxv[(b*CAND+posi)*4+3], off);
                float ia = __fmul_rn(__fsub_rn(ix2, ix1), __fsub_rn(iy2, iy1));
                for (int m = i + 1 + lane; m < cnt; m += 32){
                    if (!skfb[m]) continue;
                    int pos = g_rank2pos[b*CAND + slist[m]];
                    float mx1 = __fadd_rn(g_boxv[(b*CAND+pos)*4+0], off);
                    float my1 = __fadd_rn(g_boxv[(b*CAND+pos)*4+1], off);
                    float mx2 = __fadd_rn(g_boxv[(b*CAND+pos)*4+2], off);
                    float my2 = __fadd_rn(g_boxv[(b*CAND+pos)*4+3], off);
                    float xx1 = fmaxf(ix1, mx1), yy1 = fmaxf(iy1, my1);
                    float xx2 = fminf(ix2, mx2), yy2 = fminf(iy2, my2);
                    float ww = fmaxf(__fsub_rn(xx2, xx1), 0.0f);
                    float hh = fmaxf(__fsub_rn(yy2, yy1), 0.0f);
                    float inter = __fmul_rn(ww, hh);
                    float ma  = __fmul_rn(__fsub_rn(mx2, mx1), __fsub_rn(my2, my1));
                    float uni = __fsub_rn(__fadd_rn(ia, ma), inter);
                    if (inter / uni > NMS_T) skfb[m] = 0;
                }
            }
            __syncwarp();
        }
        for (int m = lane; m < cnt; m += 32)
            g_keep[b*CAND + slist[m]] = skfb[m];
    }
}

// per image: emit top-100 kept (rank order), pad with non-kept (rank order, score -1)
__global__ __launch_bounds__(1024) void k_final(float* __restrict__ out){
    const int b = blockIdx.x, tid = threadIdx.x;
    __shared__ int ps[1024];

    int flags[3]; int loc = 0;
    #pragma unroll
    for (int w = 0; w < 3; ++w){
        int r = tid*3 + w;
        int f = 0;
        if (r < CAND)
            f = (g_keep[b*CAND + r] && (g_ss[b*CAND + r] > 0.0f)) ? 1 : 0;
        flags[w] = f; loc += f;
    }
    ps[tid] = loc; __syncthreads();
    for (int o = 1; o < 1024; o <<= 1){
        int t = (tid >= o) ? ps[tid - o] : 0;
        __syncthreads();
        ps[tid] += t;
        __syncthreads();
    }
    const int excl  = ps[tid] - loc;
    const int total = ps[1023];

    int s = excl;
    #pragma unroll
    for (int w = 0; w < 3; ++w){
        int r = tid*3 + w;
        if (r < CAND && flags[w]){
            if (s < DETS){
                int pos = g_rank2pos[b*CAND + r];
                float* ob = out + ((size_t)b*DETS + s)*4;
                ob[0] = g_boxv[(b*CAND+pos)*4+0];
                ob[1] = g_boxv[(b*CAND+pos)*4+1];
                ob[2] = g_boxv[(b*CAND+pos)*4+2];
                ob[3] = g_boxv[(b*CAND+pos)*4+3];
                out[NB*DETS*4 + b*DETS + s]           = g_ss[b*CAND + r];
                out[NB*DETS*4 + NB*DETS + b*DETS + s] = (float)g_labelv[b*CAND+pos];
            }
            s++;
        }
    }
    const int base = (total < DETS) ? total : DETS;
    __syncthreads();

    loc = 0; int pflags[3];
    #pragma unroll
    for (int w = 0; w < 3; ++w){
        int r = tid*3 + w;
        int f = (r < CAND && !flags[w]) ? 1 : 0;
        pflags[w] = f; loc += f;
    }
    ps[tid] = loc; __syncthreads();
    for (int o = 1; o < 1024; o <<= 1){
        int t = (tid >= o) ? ps[tid - o] : 0;
        __syncthreads();
        ps[tid] += t;
        __syncthreads();
    }
    int pexcl = ps[tid] - loc;
    s = base + pexcl;
    #pragma unroll
    for (int w = 0; w < 3; ++w){
        int r = tid*3 + w;
        if (r < CAND && pflags[w]){
            if (s < DETS){
                int pos = g_rank2pos[b*CAND + r];
                float* ob = out + ((size_t)b*DETS + s)*4;
                ob[0] = g_boxv[(b*CAND+pos)*4+0];
                ob[1] = g_boxv[(b*CAND+pos)*4+1];
                ob[2] = g_boxv[(b*CAND+pos)*4+2];
                ob[3] = g_boxv[(b*CAND+pos)*4+3];
                out[NB*DETS*4 + b*DETS + s]           = -1.0f;
                out[NB*DETS*4 + NB*DETS + b*DETS + s] = (float)g_labelv[b*CAND+pos];
            }
            s++;
        }
    }
}

// ---------------- host ----------------
extern "C" void kernel_launch(void* const* d_in, const int* in_sizes, int n_in,
                              void* d_out, int out_size){
    const float *cls[3], *reg[3], *ctr[3], *anc[3];
    if (n_in >= 12 && in_sizes[0] == 2621440 && in_sizes[1] == 131072){
        for (int l = 0; l < 3; ++l){
            cls[l] = (const float*)d_in[4*l + 0];
            reg[l] = (const float*)d_in[4*l + 1];
            ctr[l] = (const float*)d_in[4*l + 2];
            anc[l] = (const float*)d_in[4*l + 3];
        }
    } else if (n_in >= 12 && in_sizes[0] == 16384){
        for (int l = 0; l < 3; ++l){
            anc[l] = (const float*)d_in[0 + l];
            cls[l] = (const float*)d_in[3 + l];
            ctr[l] = (const float*)d_in[6 + l];
            reg[l] = (const float*)d_in[9 + l];
        }
    } else {
        for (int l = 0; l < 3; ++l){
            cls[l] = (const float*)d_in[0 + l];
            reg[l] = (const float*)d_in[3 + l];
            ctr[l] = (const float*)d_in[6 + l];
            anc[l] = (const float*)d_in[9 + l];
        }
    }

    static int attr_done = 0;
    if (!attr_done){
        cudaFuncSetAttribute(k_sortlevel, cudaFuncAttributeMaxDynamicSharedMemorySize, DYNBYTES);
        attr_done = 1;
    }

    k_scores<<<dim3(TOT/2048, NB), 256>>>(cls[0], cls[1], cls[2], ctr[0], ctr[1], ctr[2]);
    k_sortlevel<<<NPAIR, 1024, DYNBYTES>>>(cls[0], cls[1], cls[2], ctr[0], ctr[1], ctr[2],
                                           reg[0], reg[1], reg[2], anc[0], anc[1], anc[2]);
    k_merge<<<NPAIR, 1024>>>();
    k_nms<<<NB*NC, 32>>>();
    k_final<<<NB, 1024>>>((float*)d_out);
}